// round 1
// baseline (speedup 1.0000x reference)
#include <cuda_runtime.h>

// ---------------------------------------------------------------------------
// ConfidenceAwareSSIM: B=16, C=3, H=W=512, fp32.
// loss = mean( clip(1 - SSIM(x,y), 0, 1) * conf ), SSIM via 11x11 Gaussian
// window (sigma=1.5), zero padding, depthwise.
//
// Strategy: fused single kernel. 64x32 output tile + 5px halo per block.
// Separable conv: horizontal pass (x, y, x^2, y^2, xy) into smem, vertical
// pass in registers. Gaussian taps are compile-time literals so ptxas emits
// FFMA-imm (rt_SMSP=1 on sm_103a, 2x the 3-reg form); symmetric pairs use
// FADD (alu pipe) + FFMA-imm (fma pipe) to split across both pipes.
// Channels looped inside the block so conf is loaded once per pixel.
// ---------------------------------------------------------------------------

#define BATCH 16
#define CH    3
#define HH    512
#define WW    512

#define TW    64          // tile output width
#define TH    32          // tile output height
#define HALO  5
#define SH    (TH + 2*HALO)   // 42 smem rows
#define SWID  (TW + 2*HALO)   // 74 smem cols (raw)
#define SPITCH 76             // raw pitch (multiple of 4 floats for LDS.128)

#define SMEM_FLOATS (2*SH*SPITCH + 5*SH*TW)
#define SMEM_BYTES  (SMEM_FLOATS * 4)

// Gaussian window g = exp(-(i-5)^2/4.5), normalized; symmetric -> 6 values.
// Computed in extended precision, embedded as literals (enables FFMA-imm).
__device__ __forceinline__ constexpr float gw(int k) {
    // k in [0,10]; symmetric
    const int d = (k <= 5) ? k : (10 - k);
    return (d == 0) ? 0.00102838f
         : (d == 1) ? 0.00759876f
         : (d == 2) ? 0.03600078f
         : (d == 3) ? 0.10936070f
         : (d == 4) ? 0.21300554f
         :            0.26601173f;
}

__global__ void zero_out_kernel(float* p) { *p = 0.0f; }

__global__ void __launch_bounds__(256, 2)
ssim_tile_kernel(const float* __restrict__ gx, const float* __restrict__ gy,
                 const float* __restrict__ gconf, float* __restrict__ gout)
{
    extern __shared__ float smem[];
    float* sx = smem;                       // [SH][SPITCH]
    float* sy = smem + SH * SPITCH;         // [SH][SPITCH]
    float* sh = smem + 2 * SH * SPITCH;     // [5][SH][TW]

    const int tid = threadIdx.x;
    const int tx  = tid & 31;   // column-pair index: cols 2*tx, 2*tx+1
    const int ty  = tid >> 5;   // row-quad index:   rows 4*ty .. 4*ty+3
    const int x0  = blockIdx.x * TW;
    const int y0  = blockIdx.y * TH;
    const int b   = blockIdx.z;

    const float C1c = 0.0001f;   // 0.01^2
    const float C2c = 0.0009f;   // 0.03^2

    float lsum[8];               // per-pixel loss accumulated over channels
#pragma unroll
    for (int i = 0; i < 8; ++i) lsum[i] = 0.0f;

    for (int c = 0; c < CH; ++c) {
        const float* xb = gx + (size_t)(b * CH + c) * (HH * WW);
        const float* yb = gy + (size_t)(b * CH + c) * (HH * WW);

        // ---- Phase 0: load x,y halo tile (zero-padded at image edges) ----
        for (int u = tid; u < SH * SWID; u += 256) {
            const int r  = u / SWID;
            const int cc = u - r * SWID;
            const int grow = y0 + r  - HALO;
            const int gcol = x0 + cc - HALO;
            float vx = 0.0f, vy = 0.0f;
            if ((unsigned)grow < (unsigned)HH && (unsigned)gcol < (unsigned)WW) {
                const size_t gi = (size_t)grow * WW + gcol;
                vx = xb[gi];
                vy = yb[gi];
            }
            sx[r * SPITCH + cc] = vx;
            sy[r * SPITCH + cc] = vy;
        }
        __syncthreads();

        // ---- Phase 1: horizontal conv of {x,y,xx,yy,xy} -> sh ----
        // Each work unit = one smem row, 4 consecutive output columns.
        for (int u = tid; u < SH * 16; u += 256) {
            const int r = u >> 4;
            const int g = u & 15;
            const float4* px = reinterpret_cast<const float4*>(sx + r * SPITCH + 4 * g);
            const float4* py = reinterpret_cast<const float4*>(sy + r * SPITCH + 4 * g);
            float vx[16], vy[16];
#pragma unroll
            for (int q = 0; q < 4; ++q) {
                const float4 a = px[q];
                vx[4*q+0] = a.x; vx[4*q+1] = a.y; vx[4*q+2] = a.z; vx[4*q+3] = a.w;
                const float4 bq = py[q];
                vy[4*q+0] = bq.x; vy[4*q+1] = bq.y; vy[4*q+2] = bq.z; vy[4*q+3] = bq.w;
            }
            // squares/products computed once per loaded value (taps 0..13 used)
            float xx[14], yy[14], xy[14];
#pragma unroll
            for (int i = 0; i < 14; ++i) {
                xx[i] = vx[i] * vx[i];
                yy[i] = vy[i] * vy[i];
                xy[i] = vx[i] * vy[i];
            }
#pragma unroll
            for (int j = 0; j < 4; ++j) {
                float hx  = gw(5) * vx[j+5];
                float hy  = gw(5) * vy[j+5];
                float hxx = gw(5) * xx[j+5];
                float hyy = gw(5) * yy[j+5];
                float hxy = gw(5) * xy[j+5];
#pragma unroll
                for (int k = 0; k < 5; ++k) {   // symmetric pairs
                    hx  += gw(k) * (vx[j+k] + vx[j+10-k]);
                    hy  += gw(k) * (vy[j+k] + vy[j+10-k]);
                    hxx += gw(k) * (xx[j+k] + xx[j+10-k]);
                    hyy += gw(k) * (yy[j+k] + yy[j+10-k]);
                    hxy += gw(k) * (xy[j+k] + xy[j+10-k]);
                }
                const int o = r * TW + 4 * g + j;
                sh[0*(SH*TW) + o] = hx;
                sh[1*(SH*TW) + o] = hy;
                sh[2*(SH*TW) + o] = hxx;
                sh[3*(SH*TW) + o] = hyy;
                sh[4*(SH*TW) + o] = hxy;
            }
        }
        __syncthreads();

        // ---- Phase 2: vertical conv (registers) + SSIM ----
        // Thread covers 4 rows x 2 cols; 14 smem rows feed 4 outputs.
        float res[5][8];
#pragma unroll
        for (int a = 0; a < 5; ++a) {
            const float* base = sh + a * (SH * TW) + 2 * tx;
            float2 v[14];
#pragma unroll
            for (int r = 0; r < 14; ++r)
                v[r] = *reinterpret_cast<const float2*>(base + (4 * ty + r) * TW);
#pragma unroll
            for (int j = 0; j < 4; ++j) {
                float ax = gw(5) * v[j+5].x;
                float ay = gw(5) * v[j+5].y;
#pragma unroll
                for (int k = 0; k < 5; ++k) {
                    ax += gw(k) * (v[j+k].x + v[j+10-k].x);
                    ay += gw(k) * (v[j+k].y + v[j+10-k].y);
                }
                res[a][2*j+0] = ax;
                res[a][2*j+1] = ay;
            }
        }

#pragma unroll
        for (int p = 0; p < 8; ++p) {
            const float mux = res[0][p], muy = res[1][p];
            const float exx = res[2][p], eyy = res[3][p], exy = res[4][p];
            const float mx2 = mux * mux, my2 = muy * muy, mxy = mux * muy;
            const float sx2 = exx - mx2, sy2 = eyy - my2, sxy = exy - mxy;
            const float num = (2.0f * mxy + C1c) * (2.0f * sxy + C2c);
            const float den = (mx2 + my2 + C1c) * (sx2 + sy2 + C2c);
            const float ssim = __fdividef(num, den);
            float loss = 1.0f - ssim;
            loss = fminf(fmaxf(loss, 0.0f), 1.0f);
            lsum[p] += loss;
        }
        __syncthreads();   // before next channel overwrites smem
    }

    // ---- conf weighting + reduction ----
    float tsum = 0.0f;
    const float* cb = gconf + (size_t)b * (HH * WW);
#pragma unroll
    for (int j = 0; j < 4; ++j) {
        const int grow = y0 + 4 * ty + j;
        const int gcol = x0 + 2 * tx;
        const float2 cv = *reinterpret_cast<const float2*>(cb + (size_t)grow * WW + gcol);
        tsum += lsum[2*j+0] * cv.x + lsum[2*j+1] * cv.y;
    }
#pragma unroll
    for (int off = 16; off > 0; off >>= 1)
        tsum += __shfl_down_sync(0xffffffffu, tsum, off);

    __shared__ float wsum[8];
    if (tx == 0) wsum[ty] = tsum;
    __syncthreads();
    if (tid == 0) {
        float s = 0.0f;
#pragma unroll
        for (int i = 0; i < 8; ++i) s += wsum[i];
        const float inv_n = 1.0f / (float)(BATCH * CH * HH * WW);
        atomicAdd(gout, s * inv_n);
    }
}

extern "C" void kernel_launch(void* const* d_in, const int* in_sizes, int n_in,
                              void* d_out, int out_size)
{
    const float* x    = (const float*)d_in[0];
    const float* y    = (const float*)d_in[1];
    const float* conf = (const float*)d_in[2];
    float* out = (float*)d_out;

    cudaFuncSetAttribute(ssim_tile_kernel,
                         cudaFuncAttributeMaxDynamicSharedMemorySize, SMEM_BYTES);

    zero_out_kernel<<<1, 1>>>(out);

    dim3 grid(WW / TW, HH / TH, BATCH);   // 8 x 16 x 16 = 2048 blocks
    ssim_tile_kernel<<<grid, 256, SMEM_BYTES>>>(x, y, conf, out);
}

// round 2
// speedup vs baseline: 1.2578x; 1.2578x over previous
#include <cuda_runtime.h>

// ---------------------------------------------------------------------------
// ConfidenceAwareSSIM: B=16, C=3, H=W=512, fp32.
// loss = mean( clip(1 - SSIM(x,y), 0, 1) * conf ), 11x11 Gaussian, zero pad.
//
// R2 changes vs R1 (127us):
//  * s/d transform (s=x+y, d=x-y): SSIM needs only conv(s), conv(d),
//    conv(s^2), conv(d^2)  ->  4 convolutions instead of 5 (-20% FMA/LDS),
//    and 2 squares per loaded value instead of 3 products.
//  * smem 77KB -> 68.5KB and __launch_bounds__(256,3): 3 CTAs/SM (occ 37.5%).
// ---------------------------------------------------------------------------

#define BATCH 16
#define CH    3
#define HH    512
#define WW    512

#define TW    64
#define TH    32
#define HALO  5
#define SH    (TH + 2*HALO)   // 42
#define SWID  (TW + 2*HALO)   // 74
#define SPITCH 76             // multiple of 4 floats for LDS.128

#define NARR  4               // S, D, A=conv(s^2), B=conv(d^2)
#define SMEM_FLOATS (2*SH*SPITCH + NARR*SH*TW)
#define SMEM_BYTES  (SMEM_FLOATS * 4)   // 68,544 B

// Gaussian taps (symmetric, normalized), as literals -> FFMA-imm (rt=1).
__device__ __forceinline__ constexpr float gw(int k) {
    const int d = (k <= 5) ? k : (10 - k);
    return (d == 0) ? 0.00102838f
         : (d == 1) ? 0.00759876f
         : (d == 2) ? 0.03600078f
         : (d == 3) ? 0.10936070f
         : (d == 4) ? 0.21300554f
         :            0.26601173f;
}

__global__ void zero_out_kernel(float* p) { *p = 0.0f; }

__global__ void __launch_bounds__(256, 3)
ssim_tile_kernel(const float* __restrict__ gx, const float* __restrict__ gy,
                 const float* __restrict__ gconf, float* __restrict__ gout)
{
    extern __shared__ float smem[];
    float* ss = smem;                       // s = x+y   [SH][SPITCH]
    float* sd = smem + SH * SPITCH;         // d = x-y   [SH][SPITCH]
    float* sh = smem + 2 * SH * SPITCH;     // [4][SH][TW]

    const int tid = threadIdx.x;
    const int tx  = tid & 31;   // cols 2*tx, 2*tx+1
    const int ty  = tid >> 5;   // rows 4*ty .. 4*ty+3
    const int x0  = blockIdx.x * TW;
    const int y0  = blockIdx.y * TH;
    const int b   = blockIdx.z;

    const float C1c = 0.0001f;   // 0.01^2
    const float C2c = 0.0009f;   // 0.03^2

    float lsum[8];
#pragma unroll
    for (int i = 0; i < 8; ++i) lsum[i] = 0.0f;

    for (int c = 0; c < CH; ++c) {
        const float* xb = gx + (size_t)(b * CH + c) * (HH * WW);
        const float* yb = gy + (size_t)(b * CH + c) * (HH * WW);

        // ---- Phase 0: load halo tile, store s=x+y, d=x-y (zero-padded) ----
        for (int u = tid; u < SH * SWID; u += 256) {
            const int r  = u / SWID;
            const int cc = u - r * SWID;
            const int grow = y0 + r  - HALO;
            const int gcol = x0 + cc - HALO;
            float vx = 0.0f, vy = 0.0f;
            if ((unsigned)grow < (unsigned)HH && (unsigned)gcol < (unsigned)WW) {
                const size_t gi = (size_t)grow * WW + gcol;
                vx = xb[gi];
                vy = yb[gi];
            }
            ss[r * SPITCH + cc] = vx + vy;
            sd[r * SPITCH + cc] = vx - vy;
        }
        __syncthreads();

        // ---- Phase 1: horizontal conv of {s, d, s^2, d^2} -> sh ----
        for (int u = tid; u < SH * 16; u += 256) {
            const int r = u >> 4;
            const int g = u & 15;
            const float4* ps = reinterpret_cast<const float4*>(ss + r * SPITCH + 4 * g);
            const float4* pd = reinterpret_cast<const float4*>(sd + r * SPITCH + 4 * g);
            float vs[16], vd[16];
#pragma unroll
            for (int q = 0; q < 4; ++q) {
                const float4 a = ps[q];
                vs[4*q+0] = a.x; vs[4*q+1] = a.y; vs[4*q+2] = a.z; vs[4*q+3] = a.w;
                const float4 bq = pd[q];
                vd[4*q+0] = bq.x; vd[4*q+1] = bq.y; vd[4*q+2] = bq.z; vd[4*q+3] = bq.w;
            }
            float s2[14], d2[14];
#pragma unroll
            for (int i = 0; i < 14; ++i) {
                s2[i] = vs[i] * vs[i];
                d2[i] = vd[i] * vd[i];
            }
#pragma unroll
            for (int j = 0; j < 4; ++j) {
                float hs  = gw(5) * vs[j+5];
                float hd  = gw(5) * vd[j+5];
                float hs2 = gw(5) * s2[j+5];
                float hd2 = gw(5) * d2[j+5];
#pragma unroll
                for (int k = 0; k < 5; ++k) {   // symmetric pairs
                    hs  += gw(k) * (vs[j+k] + vs[j+10-k]);
                    hd  += gw(k) * (vd[j+k] + vd[j+10-k]);
                    hs2 += gw(k) * (s2[j+k] + s2[j+10-k]);
                    hd2 += gw(k) * (d2[j+k] + d2[j+10-k]);
                }
                const int o = r * TW + 4 * g + j;
                sh[0*(SH*TW) + o] = hs;
                sh[1*(SH*TW) + o] = hd;
                sh[2*(SH*TW) + o] = hs2;
                sh[3*(SH*TW) + o] = hd2;
            }
        }
        __syncthreads();

        // ---- Phase 2: vertical conv (registers) + SSIM ----
        float res[NARR][8];
#pragma unroll
        for (int a = 0; a < NARR; ++a) {
            const float* base = sh + a * (SH * TW) + 2 * tx;
            float2 v[14];
#pragma unroll
            for (int r = 0; r < 14; ++r)
                v[r] = *reinterpret_cast<const float2*>(base + (4 * ty + r) * TW);
#pragma unroll
            for (int j = 0; j < 4; ++j) {
                float ax = gw(5) * v[j+5].x;
                float ay = gw(5) * v[j+5].y;
#pragma unroll
                for (int k = 0; k < 5; ++k) {
                    ax += gw(k) * (v[j+k].x + v[j+10-k].x);
                    ay += gw(k) * (v[j+k].y + v[j+10-k].y);
                }
                res[a][2*j+0] = ax;
                res[a][2*j+1] = ay;
            }
        }

#pragma unroll
        for (int p = 0; p < 8; ++p) {
            const float S = res[0][p], D = res[1][p];
            const float A = res[2][p], B = res[3][p];
            const float P = S * S, Q = D * D;
            const float t1 = 0.5f * (P - Q);        // 2*mu_x*mu_y
            const float t3 = 0.5f * (P + Q);        // mu_x^2 + mu_y^2
            const float t2 = 0.5f * (A - B) - t1;   // 2*sigma_xy
            const float t4 = 0.5f * (A + B) - t3;   // sigma_x^2 + sigma_y^2
            const float num = (t1 + C1c) * (t2 + C2c);
            const float den = (t3 + C1c) * (t4 + C2c);
            const float ssim = __fdividef(num, den);
            float loss = 1.0f - ssim;
            loss = fminf(fmaxf(loss, 0.0f), 1.0f);
            lsum[p] += loss;
        }
        __syncthreads();   // before next channel overwrites smem
    }

    // ---- conf weighting + reduction ----
    float tsum = 0.0f;
    const float* cb = gconf + (size_t)b * (HH * WW);
#pragma unroll
    for (int j = 0; j < 4; ++j) {
        const int grow = y0 + 4 * ty + j;
        const int gcol = x0 + 2 * tx;
        const float2 cv = *reinterpret_cast<const float2*>(cb + (size_t)grow * WW + gcol);
        tsum += lsum[2*j+0] * cv.x + lsum[2*j+1] * cv.y;
    }
#pragma unroll
    for (int off = 16; off > 0; off >>= 1)
        tsum += __shfl_down_sync(0xffffffffu, tsum, off);

    __shared__ float wsum[8];
    if (tx == 0) wsum[ty] = tsum;
    __syncthreads();
    if (tid == 0) {
        float s = 0.0f;
#pragma unroll
        for (int i = 0; i < 8; ++i) s += wsum[i];
        const float inv_n = 1.0f / (float)(BATCH * CH * HH * WW);
        atomicAdd(gout, s * inv_n);
    }
}

extern "C" void kernel_launch(void* const* d_in, const int* in_sizes, int n_in,
                              void* d_out, int out_size)
{
    const float* x    = (const float*)d_in[0];
    const float* y    = (const float*)d_in[1];
    const float* conf = (const float*)d_in[2];
    float* out = (float*)d_out;

    cudaFuncSetAttribute(ssim_tile_kernel,
                         cudaFuncAttributeMaxDynamicSharedMemorySize, SMEM_BYTES);

    zero_out_kernel<<<1, 1>>>(out);

    dim3 grid(WW / TW, HH / TH, BATCH);   // 8 x 16 x 16 = 2048 blocks
    ssim_tile_kernel<<<grid, 256, SMEM_BYTES>>>(x, y, conf, out);
}

// round 3
// speedup vs baseline: 1.5818x; 1.2577x over previous
#include <cuda_runtime.h>

// ---------------------------------------------------------------------------
// ConfidenceAwareSSIM: B=16, C=3, H=W=512, fp32.
// loss = mean( clip(1 - SSIM(x,y), 0, 1) * conf ), 11x11 Gaussian, zero pad.
//
// R3 changes vs R2 (101us):
//  * Phase 0 (raw tile staging) deleted: horizontal conv reads x,y directly
//    from global via aligned float4 (coalesced; ~5x L1-hit reuse).
//    smem 68.5KB -> 43KB, one barrier per channel removed.
//  * __launch_bounds__(256,4): 4 CTAs/SM (occ 50%), regs capped at 64.
//  * Phase 2: 8 rows x 1 col per thread -> 18 row-loads per 8 outputs
//    (-36% phase-2 LDS bytes), coalesced conflict-free LDS.32.
// ---------------------------------------------------------------------------

#define BATCH 16
#define CH    3
#define HH    512
#define WW    512

#define TW    64
#define TH    32
#define HALO  5
#define SH    (TH + 2*HALO)       // 42

#define SMEM_FLOATS (4*SH*TW)     // 4 arrays: S, D, conv(s^2), conv(d^2)
#define SMEM_BYTES  (SMEM_FLOATS * 4)   // 43,008 B

// Gaussian taps (symmetric, normalized) as literals -> FFMA-imm (rt=1).
__device__ __forceinline__ constexpr float gw(int k) {
    const int d = (k <= 5) ? k : (10 - k);
    return (d == 0) ? 0.00102838f
         : (d == 1) ? 0.00759876f
         : (d == 2) ? 0.03600078f
         : (d == 3) ? 0.10936070f
         : (d == 4) ? 0.21300554f
         :            0.26601173f;
}

__global__ void zero_out_kernel(float* p) { *p = 0.0f; }

__global__ void __launch_bounds__(256, 4)
ssim_tile_kernel(const float* __restrict__ gx, const float* __restrict__ gy,
                 const float* __restrict__ gconf, float* __restrict__ gout)
{
    extern __shared__ float sh[];           // [4][SH][TW]

    const int tid = threadIdx.x;
    const int col = tid & 63;               // phase-2: one column per thread
    const int ry  = tid >> 6;               // phase-2: rows 8*ry .. 8*ry+7
    const int x0  = blockIdx.x * TW;
    const int y0  = blockIdx.y * TH;
    const int b   = blockIdx.z;

    const float C1c = 0.0001f;   // 0.01^2
    const float C2c = 0.0009f;   // 0.03^2

    float lsum[8];
#pragma unroll
    for (int i = 0; i < 8; ++i) lsum[i] = 0.0f;

    for (int c = 0; c < CH; ++c) {
        const float* xb = gx + (size_t)(b * CH + c) * (HH * WW);
        const float* yb = gy + (size_t)(b * CH + c) * (HH * WW);

        // ---- Phase 1: horizontal conv of {s,d,s^2,d^2} from GLOBAL -> sh ----
        // Unit (r,g): smem row r, output cols 4g..4g+3. Taps span image cols
        // x0+4g-5 .. x0+4g+8, covered by 5 aligned float4s starting x0+4g-8.
        for (int u = tid; u < SH * 16; u += 256) {
            const int r = u >> 4;
            const int g = u & 15;
            const int grow = y0 + r - HALO;
            const bool rok = (unsigned)grow < (unsigned)HH;
            const float4* xrow = reinterpret_cast<const float4*>(xb + (size_t)grow * WW);
            const float4* yrow = reinterpret_cast<const float4*>(yb + (size_t)grow * WW);
            const int c0 = x0 + 4 * g - 8;     // first float4 col (multiple of 4)

            float vs[20], vd[20];
#pragma unroll
            for (int q = 0; q < 5; ++q) {
                const int gc = c0 + 4 * q;
                float4 fx = make_float4(0.f, 0.f, 0.f, 0.f);
                float4 fy = make_float4(0.f, 0.f, 0.f, 0.f);
                if (rok && (unsigned)gc < (unsigned)WW) {
                    fx = xrow[gc >> 2];
                    fy = yrow[gc >> 2];
                }
                vs[4*q+0] = fx.x + fy.x;  vd[4*q+0] = fx.x - fy.x;
                vs[4*q+1] = fx.y + fy.y;  vd[4*q+1] = fx.y - fy.y;
                vs[4*q+2] = fx.z + fy.z;  vd[4*q+2] = fx.z - fy.z;
                vs[4*q+3] = fx.w + fy.w;  vd[4*q+3] = fx.w - fy.w;
            }

            // conv of s and d first (store immediately to free accumulators)
#pragma unroll
            for (int j = 0; j < 4; ++j) {
                float hs = gw(5) * vs[j+8];
                float hd = gw(5) * vd[j+8];
#pragma unroll
                for (int k = 0; k < 5; ++k) {
                    hs += gw(k) * (vs[j+3+k] + vs[j+13-k]);
                    hd += gw(k) * (vd[j+3+k] + vd[j+13-k]);
                }
                const int o = r * TW + 4 * g + j;
                sh[0*(SH*TW) + o] = hs;
                sh[1*(SH*TW) + o] = hd;
            }

            // squares (span indices 3..16 -> s2[0..13]) then their conv
            float s2[14], d2[14];
#pragma unroll
            for (int i = 0; i < 14; ++i) {
                s2[i] = vs[i+3] * vs[i+3];
                d2[i] = vd[i+3] * vd[i+3];
            }
#pragma unroll
            for (int j = 0; j < 4; ++j) {
                float hs2 = gw(5) * s2[j+5];
                float hd2 = gw(5) * d2[j+5];
#pragma unroll
                for (int k = 0; k < 5; ++k) {
                    hs2 += gw(k) * (s2[j+k] + s2[j+10-k]);
                    hd2 += gw(k) * (d2[j+k] + d2[j+10-k]);
                }
                const int o = r * TW + 4 * g + j;
                sh[2*(SH*TW) + o] = hs2;
                sh[3*(SH*TW) + o] = hd2;
            }
        }
        __syncthreads();

        // ---- Phase 2: vertical conv (8 rows x 1 col per thread) + SSIM ----
        float res[4][8];
#pragma unroll
        for (int a = 0; a < 4; ++a) {
            const float* base = sh + a * (SH * TW) + col;
            float v[18];
#pragma unroll
            for (int r = 0; r < 18; ++r)
                v[r] = base[(8 * ry + r) * TW];
#pragma unroll
            for (int j = 0; j < 8; ++j) {
                float acc = gw(5) * v[j+5];
#pragma unroll
                for (int k = 0; k < 5; ++k)
                    acc += gw(k) * (v[j+k] + v[j+10-k]);
                res[a][j] = acc;
            }
        }

#pragma unroll
        for (int p = 0; p < 8; ++p) {
            const float S = res[0][p], D = res[1][p];
            const float A = res[2][p], B = res[3][p];
            const float P = S * S, Q = D * D;
            const float t1 = 0.5f * (P - Q);        // 2*mu_x*mu_y
            const float t3 = 0.5f * (P + Q);        // mu_x^2 + mu_y^2
            const float t2 = 0.5f * (A - B) - t1;   // 2*sigma_xy
            const float t4 = 0.5f * (A + B) - t3;   // sigma_x^2 + sigma_y^2
            const float num = (t1 + C1c) * (t2 + C2c);
            const float den = (t3 + C1c) * (t4 + C2c);
            const float ssim = __fdividef(num, den);
            float loss = 1.0f - ssim;
            loss = fminf(fmaxf(loss, 0.0f), 1.0f);
            lsum[p] += loss;
        }
        __syncthreads();   // phase-2 reads done before next channel overwrites
    }

    // ---- conf weighting + reduction ----
    float tsum = 0.0f;
    const float* cb = gconf + (size_t)b * (HH * WW)
                    + (size_t)(y0 + 8 * ry) * WW + (x0 + col);
#pragma unroll
    for (int j = 0; j < 8; ++j)
        tsum += lsum[j] * cb[(size_t)j * WW];

#pragma unroll
    for (int off = 16; off > 0; off >>= 1)
        tsum += __shfl_down_sync(0xffffffffu, tsum, off);

    __shared__ float wsum[8];
    if ((tid & 31) == 0) wsum[tid >> 5] = tsum;
    __syncthreads();
    if (tid == 0) {
        float s = 0.0f;
#pragma unroll
        for (int i = 0; i < 8; ++i) s += wsum[i];
        const float inv_n = 1.0f / (float)(BATCH * CH * HH * WW);
        atomicAdd(gout, s * inv_n);
    }
}

extern "C" void kernel_launch(void* const* d_in, const int* in_sizes, int n_in,
                              void* d_out, int out_size)
{
    const float* x    = (const float*)d_in[0];
    const float* y    = (const float*)d_in[1];
    const float* conf = (const float*)d_in[2];
    float* out = (float*)d_out;

    cudaFuncSetAttribute(ssim_tile_kernel,
                         cudaFuncAttributeMaxDynamicSharedMemorySize, SMEM_BYTES);

    zero_out_kernel<<<1, 1>>>(out);

    dim3 grid(WW / TW, HH / TH, BATCH);   // 8 x 16 x 16 = 2048 blocks
    ssim_tile_kernel<<<grid, 256, SMEM_BYTES>>>(x, y, conf, out);
}